// round 13
// baseline (speedup 1.0000x reference)
#include <cuda_runtime.h>
#include <cuda_bf16.h>

// out[p,o] = sum_d x[p,d]*(W[d,o] + eps[p,d,o]) + bias[o] + bias_eps[p,o]
// P=1024, D=512, O=512, fp32.
//
// HBM-bound (eps 1073.7 MB read-once). New in this round: no CTA slot idles.
// 1280 CTAs x 128 threads, one wave:
//   - CTAs [0, 256): GEMM 32x64 tile -> plain-store out = x@W+bias+bias_eps,
//     fence, flag. THEN (after gate) become stream helpers: each streams
//     d in [0, 96) for 4 rows and atomicAdds the partial into out.
//   - CTAs [256, 1280): stream eps for row p over d in [96, 512), gate on the
//     GEMM flag, then atomicAdd partial into out.
// out is accumulative after the base store; fp32 add order of the two partials
// is unordered (~1e-7 effect, << 1e-3 tol). eps read .cs. Counters self-reset.

#define PP 1024
#define DD 512
#define OO 512
#define GEMM_CTAS 256          // (1024/32 rows) * (512/64 cols)
#define D_HELP 96              // helpers cover d in [0, D_HELP)

__device__ int g_done = 0;           // GEMM CTAs that published their base tile
__device__ int g_all_done = 0;       // CTAs past the gate (reset bookkeeping)

__global__ __launch_bounds__(128)
void nes_fused(const float* __restrict__ x,
               const float* __restrict__ w,
               const float* __restrict__ bias,
               const float* __restrict__ eps,
               const float* __restrict__ bias_eps,
               float* __restrict__ out) {
    const int bid = blockIdx.x;
    const int tid = threadIdx.x;   // 0..127

    if (bid >= GEMM_CTAS) {
        // -------- stream CTA: row p, d in [D_HELP, DD) --------
        __shared__ float xs[DD];
        const int p = bid - GEMM_CTAS;

        ((float4*)xs)[tid] = ((const float4*)(x + (size_t)p * DD))[tid];
        __syncthreads();

        const float4* e = (const float4*)(eps + (size_t)p * DD * OO) + tid;

        float4 acc = make_float4(0.f, 0.f, 0.f, 0.f);
        #pragma unroll 8
        for (int d = D_HELP; d < DD; d++) {
            float4 v = __ldcs(&e[d * (OO / 4)]);   // evict-first: pure stream
            float xv = xs[d];
            acc.x = fmaf(xv, v.x, acc.x);
            acc.y = fmaf(xv, v.y, acc.y);
            acc.z = fmaf(xv, v.z, acc.z);
            acc.w = fmaf(xv, v.w, acc.w);
        }

        // ---- gate: base rows must be published (long since true) ----
        if (tid == 0) {
            volatile int* done = &g_done;
            while (*done < GEMM_CTAS) { }
        }
        __syncthreads();
        __threadfence();   // acquire

        float* orow = out + (size_t)p * OO + tid * 4;
        atomicAdd(orow + 0, acc.x);     // RED (no return)
        atomicAdd(orow + 1, acc.y);
        atomicAdd(orow + 2, acc.z);
        atomicAdd(orow + 3, acc.w);

        // ---- self-reset for next graph replay ----
        if (tid == 0) {
            int old = atomicAdd(&g_all_done, 1);
            if (old == PP + GEMM_CTAS - 1) {
                atomicExch(&g_all_done, 0);
                atomicExch(&g_done, 0);
            }
        }
    } else {
        // -------- GEMM CTA: base tile, then stream-helper --------
        __shared__ float As[16][32];
        __shared__ float Bs[16][64];
        __shared__ float hx[4][D_HELP];

        const int g  = bid;
        const int bm = (g >> 3) * 32;
        const int bn = (g & 7) * 64;
        const int tx = tid & 15;
        const int ty = tid >> 4;

        float acc[4][4];
        #pragma unroll
        for (int i = 0; i < 4; i++)
            #pragma unroll
            for (int j = 0; j < 4; j++) acc[i][j] = 0.0f;

        for (int k0 = 0; k0 < DD; k0 += 16) {
            {
                const int r  = tid >> 2;           // 0..31
                const int c4 = (tid & 3) * 4;
                float4 a = *(const float4*)&x[(size_t)(bm + r) * DD + k0 + c4];
                As[c4 + 0][r] = a.x;
                As[c4 + 1][r] = a.y;
                As[c4 + 2][r] = a.z;
                As[c4 + 3][r] = a.w;
            }
            {
                const int r  = tid >> 4;           // 0..7
                const int c4 = (tid & 15) * 4;
                *(float4*)&Bs[r][c4]     = *(const float4*)&w[(size_t)(k0 + r) * OO + bn + c4];
                *(float4*)&Bs[r + 8][c4] = *(const float4*)&w[(size_t)(k0 + r + 8) * OO + bn + c4];
            }
            __syncthreads();

            #pragma unroll
            for (int k = 0; k < 16; k++) {
                float4 a = *(const float4*)&As[k][ty * 4];
                float4 b = *(const float4*)&Bs[k][tx * 4];
                float av[4] = {a.x, a.y, a.z, a.w};
                float bv[4] = {b.x, b.y, b.z, b.w};
                #pragma unroll
                for (int i = 0; i < 4; i++)
                    #pragma unroll
                    for (int j = 0; j < 4; j++)
                        acc[i][j] = fmaf(av[i], bv[j], acc[i][j]);
            }
            __syncthreads();
        }

        // Base epilogue: out = acc + bias + bias_eps (plain store, sole writer).
        #pragma unroll
        for (int i = 0; i < 4; i++) {
            const int row = bm + ty * 4 + i;
            #pragma unroll
            for (int j = 0; j < 4; j++) {
                const int col = bn + tx * 4 + j;
                out[(size_t)row * OO + col] =
                    acc[i][j] + bias[col]
                    + __ldcs(&bias_eps[(size_t)row * OO + col]);
            }
        }

        __threadfence();   // release: publish base rows before the flag
        __syncthreads();
        if (tid == 0) atomicAdd(&g_done, 1);

        // ---- gate: all base rows published (our helper rows belong to
        //      other CTAs' tiles) ----
        if (tid == 0) {
            volatile int* done = &g_done;
            while (*done < GEMM_CTAS) { }
        }
        __syncthreads();
        __threadfence();   // acquire

        // -------- helper stream: rows 4g..4g+3, d in [0, D_HELP) --------
        const int r0 = g * 4;
        for (int idx = tid; idx < 4 * D_HELP; idx += 128)
            hx[idx / D_HELP][idx % D_HELP] = x[(size_t)(r0 + idx / D_HELP) * DD + (idx % D_HELP)];
        __syncthreads();

        #pragma unroll
        for (int i = 0; i < 4; i++) {
            const int row = r0 + i;
            const float4* e = (const float4*)(eps + (size_t)row * DD * OO) + tid;

            float4 hacc = make_float4(0.f, 0.f, 0.f, 0.f);
            #pragma unroll 8
            for (int d = 0; d < D_HELP; d++) {
                float4 v = __ldcs(&e[d * (OO / 4)]);
                float xv = hx[i][d];
                hacc.x = fmaf(xv, v.x, hacc.x);
                hacc.y = fmaf(xv, v.y, hacc.y);
                hacc.z = fmaf(xv, v.z, hacc.z);
                hacc.w = fmaf(xv, v.w, hacc.w);
            }

            float* orow = out + (size_t)row * OO + tid * 4;
            atomicAdd(orow + 0, hacc.x);
            atomicAdd(orow + 1, hacc.y);
            atomicAdd(orow + 2, hacc.z);
            atomicAdd(orow + 3, hacc.w);
        }

        // ---- self-reset bookkeeping ----
        if (tid == 0) {
            int old = atomicAdd(&g_all_done, 1);
            if (old == PP + GEMM_CTAS - 1) {
                atomicExch(&g_all_done, 0);
                atomicExch(&g_done, 0);
            }
        }
    }
}

extern "C" void kernel_launch(void* const* d_in, const int* in_sizes, int n_in,
                              void* d_out, int out_size) {
    const float* x        = (const float*)d_in[0];
    const float* w        = (const float*)d_in[1];
    const float* bias     = (const float*)d_in[2];
    const float* eps      = (const float*)d_in[3];
    const float* bias_eps = (const float*)d_in[4];
    float*       out      = (float*)d_out;

    (void)in_sizes; (void)n_in; (void)out_size;

    nes_fused<<<PP + GEMM_CTAS, 128>>>(x, w, bias, eps, bias_eps, out);
}

// round 15
// speedup vs baseline: 1.0587x; 1.0587x over previous
#include <cuda_runtime.h>
#include <cuda_bf16.h>

// out[p,o] = sum_d x[p,d]*(W[d,o] + eps[p,d,o]) + bias[o] + bias_eps[p,o]
// P=1024, D=512, O=512, fp32.
//
// TERMINAL FORM (verified best: 152.2us, DRAM 88.6%, regs 48) — at the HBM
// roofline. Mandatory DRAM traffic 1081 MB (eps 1073.7 MB read-once + x + W +
// bias_eps + out write) at the measured ~7.0 TB/s streaming plateau -> ~154us.
// Single kernel, 1280 CTAs x 128 threads, one wave:
//   - CTAs [0, 256): tiled GEMM, writes out = x@W + bias + bias_eps directly.
//     First in grid -> scheduled/retired earliest; spin-gate deadlock-free.
//   - CTAs [256, 1280): stream eps for row p (~150us, HBM-bound), gate on the
//     GEMM flag (set ~130us earlier), then out[p,:] += epsdot (L2-hot).
// eps / bias_eps read evict-first (.cs); out stored .cs. Gate spins on a
// volatile load. Counters self-reset per launch -> graph-replay deterministic.
//
// Falsified (do not revisit): 256-thr d-split (2 waves, +10us); g_xw scratch
// (+2MB write); separate combine kernel (+5us); W folded into stream CTAs
// (LTS cap); __launch_bounds__(128,9) pin (regs 48->55, worse schedule, +6us);
// GEMM-CTA stream-helpers with atomicAdd (regs 48->40, broken row locality,
// REDG pressure, +14us). DRAM 87-88.6% is the measured hard plateau.

#define PP 1024
#define DD 512
#define OO 512
#define GEMM_CTAS 256          // (1024/32 rows) * (512/64 cols)

__device__ int g_done = 0;           // GEMM CTAs completed
__device__ int g_stream_done = 0;    // stream CTAs past the gate

__global__ __launch_bounds__(128)
void nes_fused(const float* __restrict__ x,
               const float* __restrict__ w,
               const float* __restrict__ bias,
               const float* __restrict__ eps,
               const float* __restrict__ bias_eps,
               float* __restrict__ out) {
    const int bid = blockIdx.x;
    const int tid = threadIdx.x;   // 0..127

    if (bid >= GEMM_CTAS) {
        // ------------------ eps stream CTA: one row p ------------------
        __shared__ float xs[DD];
        const int p = bid - GEMM_CTAS;

        ((float4*)xs)[tid] = ((const float4*)(x + (size_t)p * DD))[tid];
        __syncthreads();

        const float4* e = (const float4*)(eps + (size_t)p * DD * OO) + tid;

        float4 acc = make_float4(0.f, 0.f, 0.f, 0.f);
        #pragma unroll 8
        for (int d = 0; d < DD; d++) {
            float4 v = __ldcs(&e[d * (OO / 4)]);   // evict-first: pure stream
            float xv = xs[d];
            acc.x = fmaf(xv, v.x, acc.x);
            acc.y = fmaf(xv, v.y, acc.y);
            acc.z = fmaf(xv, v.z, acc.z);
            acc.w = fmaf(xv, v.w, acc.w);
        }

        // ---- gate: wait for all GEMM CTAs (in practice already done) ----
        if (tid == 0) {
            volatile int* done = &g_done;
            while (*done < GEMM_CTAS) { }
        }
        __syncthreads();
        __threadfence();   // acquire: order the out-row read after the flag

        // out[p,:] currently holds x@W + bias + bias_eps (written by GEMM CTAs).
        float4* orow = (float4*)(out + (size_t)p * OO);
        float4 base = __ldcg(&orow[tid]);   // L2-hot (written ~130us earlier)

        float4 o;
        o.x = acc.x + base.x;
        o.y = acc.y + base.y;
        o.z = acc.z + base.z;
        o.w = acc.w + base.w;
        __stcs(&orow[tid], o);   // write-once stream

        // ---- self-reset for next graph replay ----
        if (tid == 0) {
            int old = atomicAdd(&g_stream_done, 1);
            if (old == PP - 1) {
                // All stream CTAs have passed the gate; safe to reset.
                atomicExch(&g_stream_done, 0);
                atomicExch(&g_done, 0);
            }
        }
    } else {
        // ---- GEMM CTA: 32x64 tile, writes out = x@W + bias + bias_eps ----
        __shared__ float As[16][32];   // [k][m]
        __shared__ float Bs[16][64];   // [k][n]

        const int g  = bid;
        const int bm = (g >> 3) * 32;
        const int bn = (g & 7) * 64;
        const int tx = tid & 15;
        const int ty = tid >> 4;

        float acc[4][4];
        #pragma unroll
        for (int i = 0; i < 4; i++)
            #pragma unroll
            for (int j = 0; j < 4; j++) acc[i][j] = 0.0f;

        for (int k0 = 0; k0 < DD; k0 += 16) {
            {
                const int r  = tid >> 2;           // 0..31
                const int c4 = (tid & 3) * 4;      // 0,4,8,12
                float4 a = *(const float4*)&x[(size_t)(bm + r) * DD + k0 + c4];
                As[c4 + 0][r] = a.x;
                As[c4 + 1][r] = a.y;
                As[c4 + 2][r] = a.z;
                As[c4 + 3][r] = a.w;
            }
            {
                const int r  = tid >> 4;           // 0..7
                const int c4 = (tid & 15) * 4;
                *(float4*)&Bs[r][c4]     = *(const float4*)&w[(size_t)(k0 + r) * OO + bn + c4];
                *(float4*)&Bs[r + 8][c4] = *(const float4*)&w[(size_t)(k0 + r + 8) * OO + bn + c4];
            }
            __syncthreads();

            #pragma unroll
            for (int k = 0; k < 16; k++) {
                float4 a = *(const float4*)&As[k][ty * 4];
                float4 b = *(const float4*)&Bs[k][tx * 4];
                float av[4] = {a.x, a.y, a.z, a.w};
                float bv[4] = {b.x, b.y, b.z, b.w};
                #pragma unroll
                for (int i = 0; i < 4; i++)
                    #pragma unroll
                    for (int j = 0; j < 4; j++)
                        acc[i][j] = fmaf(av[i], bv[j], acc[i][j]);
            }
            __syncthreads();
        }

        // Epilogue: out = acc + bias + bias_eps (stream CTAs add epsdot later).
        #pragma unroll
        for (int i = 0; i < 4; i++) {
            const int row = bm + ty * 4 + i;
            #pragma unroll
            for (int j = 0; j < 4; j++) {
                const int col = bn + tx * 4 + j;
                out[(size_t)row * OO + col] =
                    acc[i][j] + bias[col]
                    + __ldcs(&bias_eps[(size_t)row * OO + col]);  // read-once
            }
        }

        __threadfence();   // release: publish the out rows before the flag
        __syncthreads();
        if (tid == 0) atomicAdd(&g_done, 1);
    }
}

extern "C" void kernel_launch(void* const* d_in, const int* in_sizes, int n_in,
                              void* d_out, int out_size) {
    const float* x        = (const float*)d_in[0];
    const float* w        = (const float*)d_in[1];
    const float* bias     = (const float*)d_in[2];
    const float* eps      = (const float*)d_in[3];
    const float* bias_eps = (const float*)d_in[4];
    float*       out      = (float*)d_out;

    (void)in_sizes; (void)n_in; (void)out_size;

    nes_fused<<<PP + GEMM_CTAS, 128>>>(x, w, bias, eps, bias_eps, out);
}

// round 16
// speedup vs baseline: 1.0689x; 1.0096x over previous
#include <cuda_runtime.h>
#include <cuda_bf16.h>

// out[p,o] = sum_d x[p,d]*(W[d,o] + eps[p,d,o]) + bias[o] + bias_eps[p,o]
// P=1024, D=512, O=512, fp32.
//
// TERMINAL FORM — at the HBM roofline. Verified best 152.2us; identical-source
// re-runs give 152.2/156.4/157.6 (machine noise around the 1081 MB / ~7.0 TB/s
// = ~154us traffic floor). Single kernel, 1280 CTAs x 128 threads, one wave:
//   - CTAs [0, 256): tiled GEMM, writes out = x@W + bias + bias_eps directly.
//     First in grid -> scheduled/retired earliest; spin-gate deadlock-free.
//   - CTAs [256, 1280): stream eps for row p (~150us, HBM-bound), gate on the
//     GEMM flag (set ~130us earlier), then out[p,:] += epsdot (L2-hot).
// eps / bias_eps read evict-first (.cs); out stored .cs. Gate spins on a
// volatile load. Counters self-reset per launch -> graph-replay deterministic.
//
// Falsified (do not revisit): 256-thr d-split (2 waves, +10us); g_xw scratch
// (+2MB write); separate combine kernel (+5us); W folded into stream CTAs
// (LTS cap); __launch_bounds__(128,9) pin (regs 48->55, +6us); GEMM-CTA
// stream-helpers with atomicAdd (broken row locality + REDG, +14us); 256-bit
// loads (same bytes-in-flight at same reg budget, issue not binding).
// DRAM 86-88.6% is the measured hard plateau for this access pattern.

#define PP 1024
#define DD 512
#define OO 512
#define GEMM_CTAS 256          // (1024/32 rows) * (512/64 cols)

__device__ int g_done = 0;           // GEMM CTAs completed
__device__ int g_stream_done = 0;    // stream CTAs past the gate

__global__ __launch_bounds__(128)
void nes_fused(const float* __restrict__ x,
               const float* __restrict__ w,
               const float* __restrict__ bias,
               const float* __restrict__ eps,
               const float* __restrict__ bias_eps,
               float* __restrict__ out) {
    const int bid = blockIdx.x;
    const int tid = threadIdx.x;   // 0..127

    if (bid >= GEMM_CTAS) {
        // ------------------ eps stream CTA: one row p ------------------
        __shared__ float xs[DD];
        const int p = bid - GEMM_CTAS;

        ((float4*)xs)[tid] = ((const float4*)(x + (size_t)p * DD))[tid];
        __syncthreads();

        const float4* e = (const float4*)(eps + (size_t)p * DD * OO) + tid;

        float4 acc = make_float4(0.f, 0.f, 0.f, 0.f);
        #pragma unroll 8
        for (int d = 0; d < DD; d++) {
            float4 v = __ldcs(&e[d * (OO / 4)]);   // evict-first: pure stream
            float xv = xs[d];
            acc.x = fmaf(xv, v.x, acc.x);
            acc.y = fmaf(xv, v.y, acc.y);
            acc.z = fmaf(xv, v.z, acc.z);
            acc.w = fmaf(xv, v.w, acc.w);
        }

        // ---- gate: wait for all GEMM CTAs (in practice already done) ----
        if (tid == 0) {
            volatile int* done = &g_done;
            while (*done < GEMM_CTAS) { }
        }
        __syncthreads();
        __threadfence();   // acquire: order the out-row read after the flag

        // out[p,:] currently holds x@W + bias + bias_eps (written by GEMM CTAs).
        float4* orow = (float4*)(out + (size_t)p * OO);
        float4 base = __ldcg(&orow[tid]);   // L2-hot (written ~130us earlier)

        float4 o;
        o.x = acc.x + base.x;
        o.y = acc.y + base.y;
        o.z = acc.z + base.z;
        o.w = acc.w + base.w;
        __stcs(&orow[tid], o);   // write-once stream

        // ---- self-reset for next graph replay ----
        if (tid == 0) {
            int old = atomicAdd(&g_stream_done, 1);
            if (old == PP - 1) {
                // All stream CTAs have passed the gate; safe to reset.
                atomicExch(&g_stream_done, 0);
                atomicExch(&g_done, 0);
            }
        }
    } else {
        // ---- GEMM CTA: 32x64 tile, writes out = x@W + bias + bias_eps ----
        __shared__ float As[16][32];   // [k][m]
        __shared__ float Bs[16][64];   // [k][n]

        const int g  = bid;
        const int bm = (g >> 3) * 32;
        const int bn = (g & 7) * 64;
        const int tx = tid & 15;
        const int ty = tid >> 4;

        float acc[4][4];
        #pragma unroll
        for (int i = 0; i < 4; i++)
            #pragma unroll
            for (int j = 0; j < 4; j++) acc[i][j] = 0.0f;

        for (int k0 = 0; k0 < DD; k0 += 16) {
            {
                const int r  = tid >> 2;           // 0..31
                const int c4 = (tid & 3) * 4;      // 0,4,8,12
                float4 a = *(const float4*)&x[(size_t)(bm + r) * DD + k0 + c4];
                As[c4 + 0][r] = a.x;
                As[c4 + 1][r] = a.y;
                As[c4 + 2][r] = a.z;
                As[c4 + 3][r] = a.w;
            }
            {
                const int r  = tid >> 4;           // 0..7
                const int c4 = (tid & 15) * 4;
                *(float4*)&Bs[r][c4]     = *(const float4*)&w[(size_t)(k0 + r) * OO + bn + c4];
                *(float4*)&Bs[r + 8][c4] = *(const float4*)&w[(size_t)(k0 + r + 8) * OO + bn + c4];
            }
            __syncthreads();

            #pragma unroll
            for (int k = 0; k < 16; k++) {
                float4 a = *(const float4*)&As[k][ty * 4];
                float4 b = *(const float4*)&Bs[k][tx * 4];
                float av[4] = {a.x, a.y, a.z, a.w};
                float bv[4] = {b.x, b.y, b.z, b.w};
                #pragma unroll
                for (int i = 0; i < 4; i++)
                    #pragma unroll
                    for (int j = 0; j < 4; j++)
                        acc[i][j] = fmaf(av[i], bv[j], acc[i][j]);
            }
            __syncthreads();
        }

        // Epilogue: out = acc + bias + bias_eps (stream CTAs add epsdot later).
        #pragma unroll
        for (int i = 0; i < 4; i++) {
            const int row = bm + ty * 4 + i;
            #pragma unroll
            for (int j = 0; j < 4; j++) {
                const int col = bn + tx * 4 + j;
                out[(size_t)row * OO + col] =
                    acc[i][j] + bias[col]
                    + __ldcs(&bias_eps[(size_t)row * OO + col]);  // read-once
            }
        }

        __threadfence();   // release: publish the out rows before the flag
        __syncthreads();
        if (tid == 0) atomicAdd(&g_done, 1);
    }
}

extern "C" void kernel_launch(void* const* d_in, const int* in_sizes, int n_in,
                              void* d_out, int out_size) {
    const float* x        = (const float*)d_in[0];
    const float* w        = (const float*)d_in[1];
    const float* bias     = (const float*)d_in[2];
    const float* eps      = (const float*)d_in[3];
    const float* bias_eps = (const float*)d_in[4];
    float*       out      = (float*)d_out;

    (void)in_sizes; (void)n_in; (void)out_size;

    nes_fused<<<PP + GEMM_CTAS, 128>>>(x, w, bias, eps, bias_eps, out);
}